// round 13
// baseline (speedup 1.0000x reference)
#include <cuda_runtime.h>

// Gated DeltaNet single step, folded to ONE matvec:
//   qk = q . k ;  w = q - qk*beta*k ;  out = g*(w . S[:,v]) + qk*beta*v
// One warp per (b,h), 8 warps/CTA, float4 lanes.
// Triple-buffered pipeline (prefetch distance 2), scalars computed ONCE
// and parked in smem so nothing is re-read from DRAM in the epilogue.

#define DK 128
#define DV 128
#define WARPS_PER_CTA 8
#define BATCH 8
#define NBATCH (DK / BATCH)   // 16

__global__ __launch_bounds__(WARPS_PER_CTA * 32, 2)
void deltanet_step_kernel(const float* __restrict__ q,
                          const float* __restrict__ k,
                          const float* __restrict__ v,
                          const float* __restrict__ beta,
                          const float* __restrict__ gate,
                          const float* __restrict__ state,
                          float* __restrict__ out,
                          int BH) {
    const int warp = threadIdx.x >> 5;
    const int lane = threadIdx.x & 31;
    const int bh   = blockIdx.x * WARPS_PER_CTA + warp;
    if (bh >= BH) return;

    __shared__ float  sw[WARPS_PER_CTA][DK];
    __shared__ float2 sscal[WARPS_PER_CTA];   // (qkb, g) per warp

    {
        const float4 q4 = reinterpret_cast<const float4*>(q + (size_t)bh * DK)[lane];
        const float4 k4 = reinterpret_cast<const float4*>(k + (size_t)bh * DK)[lane];

        float qk = q4.x * k4.x + q4.y * k4.y + q4.z * k4.z + q4.w * k4.w;
        #pragma unroll
        for (int off = 16; off > 0; off >>= 1)
            qk += __shfl_xor_sync(0xFFFFFFFFu, qk, off);

        const float qkb = qk * beta[bh];

        float4 w4;
        w4.x = fmaf(-qkb, k4.x, q4.x);
        w4.y = fmaf(-qkb, k4.y, q4.y);
        w4.z = fmaf(-qkb, k4.z, q4.z);
        w4.w = fmaf(-qkb, k4.w, q4.w);
        reinterpret_cast<float4*>(sw[warp])[lane] = w4;
        if (lane == 0) sscal[warp] = make_float2(qkb, gate[bh]);
        __syncwarp();
    }

    const float4* S = reinterpret_cast<const float4*>(state + (size_t)bh * (DK * DV));

    float4 acc = make_float4(0.f, 0.f, 0.f, 0.f);

    float4 bufA[BATCH];
    float4 bufB[BATCH];
    float4 bufC[BATCH];

    // Prologue: batches 0 and 1 in flight.
    #pragma unroll
    for (int i = 0; i < BATCH; ++i)
        bufA[i] = S[i * (DV / 4) + lane];
    #pragma unroll
    for (int i = 0; i < BATCH; ++i)
        bufB[i] = S[(BATCH + i) * (DV / 4) + lane];

    #pragma unroll
    for (int b = 0; b < NBATCH; ++b) {
        float4* cur = (b % 3 == 0) ? bufA : (b % 3 == 1) ? bufB : bufC;
        float4* pre = (b % 3 == 0) ? bufC : (b % 3 == 1) ? bufA : bufB;

        // Issue batch b+2 while batch b computes (b+1 is landing).
        if (b + 2 < NBATCH) {
            const int base = (b + 2) * BATCH;
            #pragma unroll
            for (int i = 0; i < BATCH; ++i)
                pre[i] = S[(base + i) * (DV / 4) + lane];
        }

        const int base = b * BATCH;
        #pragma unroll
        for (int i = 0; i < BATCH; ++i) {
            const float wc = sw[warp][base + i];
            acc.x = fmaf(wc, cur[i].x, acc.x);
            acc.y = fmaf(wc, cur[i].y, acc.y);
            acc.z = fmaf(wc, cur[i].z, acc.z);
            acc.w = fmaf(wc, cur[i].w, acc.w);
        }
    }

    // Epilogue: scalars from smem (no DRAM re-reads).
    const float2 sc  = sscal[warp];         // (qkb, g)
    const float4 vv  = reinterpret_cast<const float4*>(v + (size_t)bh * DV)[lane];

    float4 o;
    o.x = fmaf(sc.y, acc.x, sc.x * vv.x);
    o.y = fmaf(sc.y, acc.y, sc.x * vv.y);
    o.z = fmaf(sc.y, acc.z, sc.x * vv.z);
    o.w = fmaf(sc.y, acc.w, sc.x * vv.w);
    reinterpret_cast<float4*>(out + (size_t)bh * DV)[lane] = o;
}

extern "C" void kernel_launch(void* const* d_in, const int* in_sizes, int n_in,
                              void* d_out, int out_size) {
    const float* q     = (const float*)d_in[0];
    const float* k     = (const float*)d_in[1];
    const float* v     = (const float*)d_in[2];
    const float* beta  = (const float*)d_in[3];
    const float* gate  = (const float*)d_in[4];
    const float* state = (const float*)d_in[5];
    float* out = (float*)d_out;

    const int BH = in_sizes[3];   // beta: B*H elements
    const int grid = (BH + WARPS_PER_CTA - 1) / WARPS_PER_CTA;

    deltanet_step_kernel<<<grid, WARPS_PER_CTA * 32>>>(q, k, v, beta, gate, state, out, BH);
}